// round 16
// baseline (speedup 1.0000x reference)
#include <cuda_runtime.h>
#include <cuda_fp16.h>
#include <math.h>
#include <stdint.h>

// Problem constants (fixed shapes)
#define SEQ   2048
#define DIM_  3072
#define NH    24
#define HD    128
#define QKVE  9216      // (24 + 2*24) * 128
#define EPSI  1e-6f

// GEMM tiling: BM=128, BN=128, BK=32, 512 threads, 4 stages
#define QA_TILE  8192             // 128 * 64
#define QB_TILE  8192             // 128 * 64
#define QSTAGE   16384

// Flash tiling (R13 config)
#define FQ    128                 // q rows per CTA
#define FK    128                 // keys per tile
#define FS_LD 136                 // fp16 row stride (272 B)
#define KV_TILE_BYTES  34816      // 128*272
#define KV_STAGE_BYTES 69632      // K + V tiles

// Scratch (device globals, allocation-free rule). ~151 MB total.
__device__ __half g_qkv[(size_t)SEQ * QKVE];               // 37.7 MB
__device__ __half g_Ah[(size_t)SEQ * DIM_];                // 12.6 MB
__device__ __half g_Bh[(size_t)QKVE * DIM_];               // 56.6 MB (w_qkv)
__device__ __half g_Bo[(size_t)DIM_ * DIM_];               // 18.9 MB (w_out)
__device__ __half g_Qh[(size_t)SEQ * DIM_];                // 12.6 MB
__device__ __half g_Kh[(size_t)SEQ * DIM_];                // 12.6 MB

__device__ __forceinline__ uint32_t smem_to_u32(const void* p) {
    uint32_t a;
    asm("{ .reg .u64 t; cvta.to.shared.u64 t, %1; cvt.u32.u64 %0, t; }" : "=r"(a) : "l"(p));
    return a;
}
__device__ __forceinline__ void cp_async16(uint32_t dst, const void* src) {
    asm volatile("cp.async.cg.shared.global [%0], [%1], 16;" :: "r"(dst), "l"(src) : "memory");
}
__device__ __forceinline__ void ldm_x4(uint32_t* r, uint32_t addr) {
    asm volatile("ldmatrix.sync.aligned.m8n8.x4.shared.b16 {%0,%1,%2,%3}, [%4];"
        : "=r"(r[0]), "=r"(r[1]), "=r"(r[2]), "=r"(r[3]) : "r"(addr));
}
__device__ __forceinline__ void ldm_x4_t(uint32_t* r, uint32_t addr) {
    asm volatile("ldmatrix.sync.aligned.m8n8.x4.trans.shared.b16 {%0,%1,%2,%3}, [%4];"
        : "=r"(r[0]), "=r"(r[1]), "=r"(r[2]), "=r"(r[3]) : "r"(addr));
}
__device__ __forceinline__ void mma_f16(float* c, const uint32_t* a, const uint32_t* b) {
    asm volatile(
        "mma.sync.aligned.m16n8k16.row.col.f32.f16.f16.f32 "
        "{%0,%1,%2,%3}, {%4,%5,%6,%7}, {%8,%9}, {%0,%1,%2,%3};"
        : "+f"(c[0]), "+f"(c[1]), "+f"(c[2]), "+f"(c[3])
        : "r"(a[0]), "r"(a[1]), "r"(a[2]), "r"(a[3]), "r"(b[0]), "r"(b[1]));
}
__device__ __forceinline__ uint32_t pack2(float a, float b) {
    __half2 H = __floats2half2_rn(a, b);
    return *reinterpret_cast<uint32_t*>(&H);
}
__device__ __forceinline__ uint2 pack4(float4 v) {
    uint2 o;
    o.x = pack2(v.x, v.y);
    o.y = pack2(v.z, v.w);
    return o;
}
__device__ __forceinline__ float4 unpack4(uint2 u) {
    __half2 a = *reinterpret_cast<__half2*>(&u.x);
    __half2 b = *reinterpret_cast<__half2*>(&u.y);
    float2 fa = __half22float2(a), fb = __half22float2(b);
    return make_float4(fa.x, fa.y, fb.x, fb.y);
}

// ===========================================================================
// Fused fp32 -> fp16 conversion of hidden, w_qkv, w_out (one launch).
// ===========================================================================
#define N4_H   (SEQ * DIM_ / 4)      // 1572864
#define N4_WQ  (QKVE * DIM_ / 4)     // 7077888
#define N4_WO  (DIM_ * DIM_ / 4)     // 2359296
__global__ void __launch_bounds__(256) conv_all(
    const float4* __restrict__ hidden, const float4* __restrict__ wqkv,
    const float4* __restrict__ wout)
{
    int base = blockIdx.x * 512 + threadIdx.x;
    #pragma unroll
    for (int t = 0; t < 2; ++t) {
        int i = base + t * 256;
        if (i < N4_H) {
            ((uint2*)g_Ah)[i] = pack4(hidden[i]);
        } else if (i < N4_H + N4_WQ) {
            int j = i - N4_H;
            ((uint2*)g_Bh)[j] = pack4(wqkv[j]);
        } else if (i < N4_H + N4_WQ + N4_WO) {
            int j = i - N4_H - N4_WQ;
            ((uint2*)g_Bo)[j] = pack4(wout[j]);
        }
    }
}

// ===========================================================================
// GEMM: C[M,N] = Ah[M,K]*Bh[N,K]^T, fp32 acc. OUTH: fp16 out else fp32.
// BM=128, BN=128, BK=32, 512 threads (16 warps: 4M x 4N, warp tile 32x32).
// 4 warps/SMSP. cp.async 4-stage, 64B swizzled rows. Grid: (N/128, M/128).
// (Mainloop identical to the R15-validated tc_gemm_q.)
// ===========================================================================
template <bool OUTH>
__global__ void __launch_bounds__(512, 1) tc_gemm(
    const __half* __restrict__ Ah, const __half* __restrict__ Bh,
    void* __restrict__ Cv, int ldc, int K)
{
    extern __shared__ __align__(1024) char smem[];
    const uint32_t sbase = smem_to_u32(smem);

    const int tid  = threadIdx.x;
    const int wid  = tid >> 5;
    const int lane = tid & 31;
    const int wm   = wid & 3;        // 0..3 (M, 32 rows each)
    const int wn   = wid >> 2;       // 0..3 (N, 32 cols each)
    const int bm0  = blockIdx.y * 128;
    const int bn0  = blockIdx.x * 128;
    const size_t krow = (size_t)K * 2;

    const int lr  = lane & 15;
    const int lch = lane >> 4;
    const int sw  = (lr >> 1) & 3;

    float acc[2][4][4] = {};
    const int nch = K / 32;

    auto load_chunk = [&](int i, int sg) {
        const size_t kbyte = (size_t)i * 64;
        const uint32_t stb = sbase + sg * QSTAGE;
        #pragma unroll
        for (int t = 0; t < 2; ++t) {
            int lin = tid + t * 512;             // 0..1023
            const char* src;
            uint32_t dst;
            if (lin < 512) {                     // A: 128 rows x 4 ch
                int row = lin >> 2, ch = lin & 3;
                src = (const char*)Ah + (size_t)(bm0 + row) * krow + kbyte + ch * 16;
                dst = stb + row * 64 + ((ch ^ ((row >> 1) & 3)) << 4);
            } else {                             // B: 128 rows x 4 ch
                int l2  = lin - 512;
                int row = l2 >> 2, ch = l2 & 3;
                src = (const char*)Bh + (size_t)(bn0 + row) * krow + kbyte + ch * 16;
                dst = stb + QA_TILE + row * 64 + ((ch ^ ((row >> 1) & 3)) << 4);
            }
            cp_async16(dst, src);
        }
        asm volatile("cp.async.commit_group;" ::: "memory");
    };

    load_chunk(0, 0);
    load_chunk(1, 1);
    load_chunk(2, 2);

    for (int i = 0; i < nch; ++i) {
        asm volatile("cp.async.wait_group 2;" ::: "memory");
        __syncthreads();
        if (i + 3 < nch) {
            load_chunk(i + 3, (i + 3) & 3);
        } else {
            asm volatile("cp.async.commit_group;" ::: "memory");
        }

        const uint32_t st  = sbase + (i & 3) * QSTAGE;
        const uint32_t stB = st + QA_TILE;
        const int arow = (wm * 32 + lr) * 64;
        const int brow = (wn * 32 + lr) * 64;

        #pragma unroll
        for (int ks = 0; ks < 2; ++ks) {
            const uint32_t choff = (uint32_t)(((ks * 2 + lch) ^ sw) << 4);
            uint32_t a[2][4];
            uint32_t b[4][2];

            #pragma unroll
            for (int p = 0; p < 2; ++p) {
                uint32_t r[4];
                ldm_x4(r, stB + brow + p * (16 * 64) + choff);
                b[2*p][0] = r[0]; b[2*p][1] = r[2];
                b[2*p+1][0] = r[1]; b[2*p+1][1] = r[3];
            }
            #pragma unroll
            for (int ii = 0; ii < 2; ++ii)
                ldm_x4(a[ii], st + arow + ii * (16 * 64) + choff);
            #pragma unroll
            for (int ii = 0; ii < 2; ++ii)
                #pragma unroll
                for (int jj = 0; jj < 4; ++jj)
                    mma_f16(acc[ii][jj], a[ii], b[jj]);
        }
        __syncthreads();
    }

    const int r0 = bm0 + wm * 32 + (lane >> 2);
    const int c0 = bn0 + wn * 32 + (lane & 3) * 2;
    if (OUTH) {
        __half* C = (__half*)Cv;
        #pragma unroll
        for (int ii = 0; ii < 2; ++ii) {
            #pragma unroll
            for (int jj = 0; jj < 4; ++jj) {
                *(uint32_t*)(C + (size_t)(r0 + ii * 16) * ldc + c0 + jj * 8)
                    = pack2(acc[ii][jj][0], acc[ii][jj][1]);
                *(uint32_t*)(C + (size_t)(r0 + ii * 16 + 8) * ldc + c0 + jj * 8)
                    = pack2(acc[ii][jj][2], acc[ii][jj][3]);
            }
        }
    } else {
        float* C = (float*)Cv;
        #pragma unroll
        for (int ii = 0; ii < 2; ++ii) {
            #pragma unroll
            for (int jj = 0; jj < 4; ++jj) {
                float* p0 = C + (size_t)(r0 + ii * 16) * ldc + c0 + jj * 8;
                float* p1 = C + (size_t)(r0 + ii * 16 + 8) * ldc + c0 + jj * 8;
                *(float2*)p0 = make_float2(acc[ii][jj][0], acc[ii][jj][1]);
                *(float2*)p1 = make_float2(acc[ii][jj][2], acc[ii][jj][3]);
            }
        }
    }
}

// ===========================================================================
// Fused RMSNorm + RoPE (reads fp16 g_qkv). One warp per (s, slot).
// ===========================================================================
__global__ void __launch_bounds__(256) norm_rope_split(
    const float* __restrict__ cosb, const float* __restrict__ sinb,
    const float* __restrict__ wq, const float* __restrict__ wk)
{
    const int unit = blockIdx.x * 8 + (threadIdx.x >> 5);
    const int lane = threadIdx.x & 31;
    const int s    = unit / 48;
    const int slot = unit % 48;
    const int grp  = slot / 24;     // 0=q, 1=k
    const int h    = slot % 24;

    const __half* p = g_qkv + (size_t)s * QKVE + grp * 3072 + h * HD;
    float4 x = unpack4(*(const uint2*)(p + lane * 4));

    float ss = x.x * x.x + x.y * x.y + x.z * x.z + x.w * x.w;
    #pragma unroll
    for (int of = 16; of > 0; of >>= 1) ss += __shfl_xor_sync(0xffffffffu, ss, of);
    float r = rsqrtf(ss * (1.0f / 128.0f) + EPSI);

    const float* w = (grp == 0) ? wq : wk;
    float4 w4 = *(const float4*)(w + lane * 4);
    float x0 = x.x * r * w4.x, x1 = x.y * r * w4.y;
    float x2 = x.z * r * w4.z, x3 = x.w * r * w4.w;

    int i = lane * 2;
    float c0 = cosb[s * 64 + i],     s0 = sinb[s * 64 + i];
    float c1 = cosb[s * 64 + i + 1], s1 = sinb[s * 64 + i + 1];
    float4 o;
    o.x = x0 * c0 - x1 * s0;
    o.y = x1 * c0 + x0 * s0;
    o.z = x2 * c1 - x3 * s1;
    o.w = x3 * c1 + x2 * s1;

    size_t off = (size_t)s * DIM_ + h * HD + lane * 4;
    if (grp == 0) {
        const float sc = 0.08838834764831845f;  // 1/sqrt(128)
        o.x *= sc; o.y *= sc; o.z *= sc; o.w *= sc;
        *(uint2*)(g_Qh + off) = pack4(o);
    } else {
        *(uint2*)(g_Kh + off) = pack4(o);
    }
}

// ===========================================================================
// Tensor-core flash attention (R13 config): no-max softmax, 256 threads,
// FQ=128, FK=128, 2-stage KV. V read from g_qkv. (unchanged)
// ===========================================================================
__global__ void __launch_bounds__(256, 1) flash_mma(__half* __restrict__ oh)
{
    extern __shared__ char fsm[];
    const uint32_t sQ  = smem_to_u32(fsm);
    const uint32_t kvb = sQ + FQ * FS_LD * 2;

    const int head = blockIdx.y;
    const int q0   = blockIdx.x * FQ;
    const int tid  = threadIdx.x;
    const int wid  = tid >> 5;
    const int lane = tid & 31;
    const int wr0  = wid * 16;
    const size_t hoff = (size_t)head * HD;

    const __half* ksrc = g_Kh;                     // stride DIM_
    const __half* vsrc = g_qkv + 2 * NH * HD;      // stride QKVE

    #pragma unroll
    for (int i = 0; i < 8; ++i) {
        int lin = tid + i * 256;
        int row = lin >> 4, ch = lin & 15;
        cp_async16(sQ + row * (FS_LD * 2) + ch * 16,
                   g_Qh + (size_t)(q0 + row) * DIM_ + hoff + ch * 8);
    }
    #pragma unroll
    for (int i = 0; i < 16; ++i) {
        int lin = tid + i * 256;
        int sel = lin >> 11;
        int idx = lin & 2047;
        int row = idx >> 4, ch = idx & 15;
        const __half* src = sel ? (vsrc + (size_t)row * QKVE + hoff + ch * 8)
                                : (ksrc + (size_t)row * DIM_ + hoff + ch * 8);
        cp_async16(kvb + sel * KV_TILE_BYTES + row * (FS_LD * 2) + ch * 16, src);
    }
    asm volatile("cp.async.commit_group;" ::: "memory");

    float O[16][4];
    #pragma unroll
    for (int f = 0; f < 16; ++f)
        #pragma unroll
        for (int x = 0; x < 4; ++x) O[f][x] = 0.f;
    float l_a = 0.f, l_b = 0.f;

    const int lr  = lane & 15;
    const int lch = lane >> 4;
    const int g3  = lane >> 3;
    const int r8  = lane & 7;

    const int NT = SEQ / FK;                     // 16
    for (int kt = 0; kt < NT; ++kt) {
        const int s = kt & 1;
        if (kt + 1 < NT) {
            const int k0n = (kt + 1) * FK;
            const uint32_t stb = kvb + (s ^ 1) * KV_STAGE_BYTES;
            #pragma unroll
            for (int i = 0; i < 16; ++i) {
                int lin = tid + i * 256;
                int sel = lin >> 11;
                int idx = lin & 2047;
                int row = idx >> 4, ch = idx & 15;
                const __half* src = sel
                    ? (vsrc + (size_t)(k0n + row) * QKVE + hoff + ch * 8)
                    : (ksrc + (size_t)(k0n + row) * DIM_ + hoff + ch * 8);
                cp_async16(stb + sel * KV_TILE_BYTES + row * (FS_LD * 2) + ch * 16, src);
            }
            asm volatile("cp.async.commit_group;" ::: "memory");
            asm volatile("cp.async.wait_group 1;" ::: "memory");
        } else {
            asm volatile("cp.async.wait_group 0;" ::: "memory");
        }
        __syncthreads();

        const uint32_t bK = kvb + s * KV_STAGE_BYTES;
        const uint32_t bV = bK + KV_TILE_BYTES;

        float sfr[16][4];
        #pragma unroll
        for (int f = 0; f < 16; ++f)
            #pragma unroll
            for (int x = 0; x < 4; ++x) sfr[f][x] = 0.f;

        const uint32_t aQ = sQ + (wr0 + lr) * (FS_LD * 2) + lch * 16;
        #pragma unroll
        for (int ks = 0; ks < 8; ++ks) {
            uint32_t ah[4];
            ldm_x4(ah, aQ + ks * 32);
            #pragma unroll
            for (int nfp = 0; nfp < 8; ++nfp) {
                uint32_t rh[4];
                uint32_t kaddr = (nfp * 16 + lr) * (FS_LD * 2) + lch * 16 + ks * 32;
                ldm_x4(rh, bK + kaddr);
                uint32_t b0[2] = {rh[0], rh[2]}, b1[2] = {rh[1], rh[3]};
                mma_f16(sfr[2*nfp],   ah, b0);
                mma_f16(sfr[2*nfp+1], ah, b1);
            }
        }

        #pragma unroll
        for (int ka = 0; ka < 8; ++ka) {
            float* s0 = sfr[2*ka];
            float* s1 = sfr[2*ka+1];
            s0[0] = __expf(s0[0]); l_a += s0[0];
            s0[1] = __expf(s0[1]); l_a += s0[1];
            s0[2] = __expf(s0[2]); l_b += s0[2];
            s0[3] = __expf(s0[3]); l_b += s0[3];
            s1[0] = __expf(s1[0]); l_a += s1[0];
            s1[1] = __expf(s1[1]); l_a += s1[1];
            s1[2] = __expf(s1[2]); l_b += s1[2];
            s1[3] = __expf(s1[3]); l_b += s1[3];

            uint32_t pH[4];
            pH[0] = pack2(s0[0], s0[1]);
            pH[1] = pack2(s0[2], s0[3]);
            pH[2] = pack2(s1[0], s1[1]);
            pH[3] = pack2(s1[2], s1[3]);

            #pragma unroll
            for (int nop = 0; nop < 8; ++nop) {
                uint32_t vaddr = (ka * 16 + (g3 & 1) * 8 + r8) * (FS_LD * 2)
                               + (nop * 16 + (g3 >> 1) * 8) * 2;
                uint32_t vh[4];
                ldm_x4_t(vh, bV + vaddr);
                uint32_t b0[2] = {vh[0], vh[1]}, b1[2] = {vh[2], vh[3]};
                mma_f16(O[2*nop],   pH, b0);
                mma_f16(O[2*nop+1], pH, b1);
            }
        }
        __syncthreads();
    }

    l_a += __shfl_xor_sync(0xffffffffu, l_a, 1);
    l_a += __shfl_xor_sync(0xffffffffu, l_a, 2);
    l_b += __shfl_xor_sync(0xffffffffu, l_b, 1);
    l_b += __shfl_xor_sync(0xffffffffu, l_b, 2);

    const float inva = 1.0f / l_a, invb = 1.0f / l_b;
    const int ra = q0 + wr0 + (lane >> 2);
    const int rb = ra + 8;
    const int cbase = head * HD + (lane & 3) * 2;
    #pragma unroll
    for (int f = 0; f < 16; ++f) {
        int col = cbase + f * 8;
        *(uint32_t*)(oh + (size_t)ra * DIM_ + col) = pack2(O[f][0] * inva, O[f][1] * inva);
        *(uint32_t*)(oh + (size_t)rb * DIM_ + col) = pack2(O[f][2] * invb, O[f][3] * invb);
    }
}

// ---------------------------------------------------------------------------
// Launch sequence
// ---------------------------------------------------------------------------
extern "C" void kernel_launch(void* const* d_in, const int* in_sizes, int n_in,
                              void* d_out, int out_size)
{
    const float* hidden = (const float*)d_in[0];
    const float* cosb   = (const float*)d_in[2];
    const float* sinb   = (const float*)d_in[3];
    const float* w_qkv  = (const float*)d_in[4];
    const float* nq_w   = (const float*)d_in[5];
    const float* nk_w   = (const float*)d_in[6];
    const float* w_out  = (const float*)d_in[7];
    float* out = (float*)d_out;

    __half *qkv, *Ah, *Bh, *Bo;
    cudaGetSymbolAddress((void**)&qkv, g_qkv);
    cudaGetSymbolAddress((void**)&Ah,  g_Ah);
    cudaGetSymbolAddress((void**)&Bh,  g_Bh);
    cudaGetSymbolAddress((void**)&Bo,  g_Bo);

    const int q_smem = 4 * QSTAGE;                         // 65536
    cudaFuncSetAttribute((const void*)tc_gemm<true>,
                         cudaFuncAttributeMaxDynamicSharedMemorySize, q_smem);
    cudaFuncSetAttribute((const void*)tc_gemm<false>,
                         cudaFuncAttributeMaxDynamicSharedMemorySize, q_smem);
    const int fl_smem = FQ * FS_LD * 2 + 2 * KV_STAGE_BYTES;   // 174080
    cudaFuncSetAttribute(flash_mma, cudaFuncAttributeMaxDynamicSharedMemorySize, fl_smem);

    // 1) Convert hidden, w_qkv, w_out to fp16 in one launch
    {
        int n4 = N4_H + N4_WQ + N4_WO;
        conv_all<<<(n4 + 511) / 512, 256>>>(
            (const float4*)hidden, (const float4*)w_qkv, (const float4*)w_out);
    }

    // 2) QKV projection -> g_qkv (fp16)
    tc_gemm<true><<<dim3(QKVE / 128, SEQ / 128), 512, q_smem>>>(
        Ah, Bh, qkv, QKVE, DIM_);

    // 3) RMSNorm + RoPE -> g_Qh, g_Kh (V stays in g_qkv)
    norm_rope_split<<<(SEQ * 48) / 8, 256>>>(cosb, sinb, nq_w, nk_w);

    // 4) Flash attention -> fp16 into Ah
    flash_mma<<<dim3(SEQ / FQ, NH), 256, fl_smem>>>(Ah);

    // 5) Output projection -> d_out (fp32)
    tc_gemm<false><<<dim3(DIM_ / 128, SEQ / 128), 512, q_smem>>>(
        Ah, Bo, out, DIM_, DIM_);
}

// round 17
// speedup vs baseline: 1.0054x; 1.0054x over previous
#include <cuda_runtime.h>
#include <cuda_fp16.h>
#include <math.h>
#include <stdint.h>

// Problem constants (fixed shapes)
#define SEQ   2048
#define DIM_  3072
#define NH    24
#define HD    128
#define QKVE  9216      // (24 + 2*24) * 128
#define EPSI  1e-6f

// GEMM tiling (out-proj): BM=128, BN=192, BK=32, 384 threads, 4 stages
#define GA_TILE  8192             // 128 * 64
#define GB_TILE  12288            // 192 * 64
#define GNSTG    4

// GEMM tiling (QKV): BM=128, BN=128, BK=32, 512 threads, 4 stages
#define QA_TILE  8192             // 128 * 64
#define QSTAGE   16384

// Flash tiling (R13 config)
#define FQ    128                 // q rows per CTA
#define FK    128                 // keys per tile
#define FS_LD 136                 // fp16 row stride (272 B)
#define KV_TILE_BYTES  34816      // 128*272
#define KV_STAGE_BYTES 69632      // K + V tiles

// Scratch (device globals, allocation-free rule). ~151 MB total.
__device__ __half g_qkv[(size_t)SEQ * QKVE];               // 37.7 MB
__device__ __half g_Ah[(size_t)SEQ * DIM_];                // 12.6 MB
__device__ __half g_Bh[(size_t)QKVE * DIM_];               // 56.6 MB (w_qkv)
__device__ __half g_Bo[(size_t)DIM_ * DIM_];               // 18.9 MB (w_out)
__device__ __half g_Qh[(size_t)SEQ * DIM_];                // 12.6 MB
__device__ __half g_Kh[(size_t)SEQ * DIM_];                // 12.6 MB

__device__ __forceinline__ uint32_t smem_to_u32(const void* p) {
    uint32_t a;
    asm("{ .reg .u64 t; cvta.to.shared.u64 t, %1; cvt.u32.u64 %0, t; }" : "=r"(a) : "l"(p));
    return a;
}
__device__ __forceinline__ void cp_async16(uint32_t dst, const void* src) {
    asm volatile("cp.async.cg.shared.global [%0], [%1], 16;" :: "r"(dst), "l"(src) : "memory");
}
__device__ __forceinline__ void ldm_x4(uint32_t* r, uint32_t addr) {
    asm volatile("ldmatrix.sync.aligned.m8n8.x4.shared.b16 {%0,%1,%2,%3}, [%4];"
        : "=r"(r[0]), "=r"(r[1]), "=r"(r[2]), "=r"(r[3]) : "r"(addr));
}
__device__ __forceinline__ void ldm_x4_t(uint32_t* r, uint32_t addr) {
    asm volatile("ldmatrix.sync.aligned.m8n8.x4.trans.shared.b16 {%0,%1,%2,%3}, [%4];"
        : "=r"(r[0]), "=r"(r[1]), "=r"(r[2]), "=r"(r[3]) : "r"(addr));
}
__device__ __forceinline__ void mma_f16(float* c, const uint32_t* a, const uint32_t* b) {
    asm volatile(
        "mma.sync.aligned.m16n8k16.row.col.f32.f16.f16.f32 "
        "{%0,%1,%2,%3}, {%4,%5,%6,%7}, {%8,%9}, {%0,%1,%2,%3};"
        : "+f"(c[0]), "+f"(c[1]), "+f"(c[2]), "+f"(c[3])
        : "r"(a[0]), "r"(a[1]), "r"(a[2]), "r"(a[3]), "r"(b[0]), "r"(b[1]));
}
__device__ __forceinline__ uint32_t pack2(float a, float b) {
    __half2 H = __floats2half2_rn(a, b);
    return *reinterpret_cast<uint32_t*>(&H);
}
__device__ __forceinline__ uint2 pack4(float4 v) {
    uint2 o;
    o.x = pack2(v.x, v.y);
    o.y = pack2(v.z, v.w);
    return o;
}
__device__ __forceinline__ float4 unpack4(uint2 u) {
    __half2 a = *reinterpret_cast<__half2*>(&u.x);
    __half2 b = *reinterpret_cast<__half2*>(&u.y);
    float2 fa = __half22float2(a), fb = __half22float2(b);
    return make_float4(fa.x, fa.y, fb.x, fb.y);
}

// ===========================================================================
// Fused fp32 -> fp16 conversion of hidden, w_qkv, w_out (one launch).
// Each thread converts 4 float4s (MLP=4).
// ===========================================================================
#define N4_H   (SEQ * DIM_ / 4)      // 1572864
#define N4_WQ  (QKVE * DIM_ / 4)     // 7077888
#define N4_WO  (DIM_ * DIM_ / 4)     // 2359296
__global__ void __launch_bounds__(256) conv_all(
    const float4* __restrict__ hidden, const float4* __restrict__ wqkv,
    const float4* __restrict__ wout)
{
    int base = blockIdx.x * 1024 + threadIdx.x;
    #pragma unroll
    for (int t = 0; t < 4; ++t) {
        int i = base + t * 256;
        if (i < N4_H) {
            ((uint2*)g_Ah)[i] = pack4(hidden[i]);
        } else if (i < N4_H + N4_WQ) {
            int j = i - N4_H;
            ((uint2*)g_Bh)[j] = pack4(wqkv[j]);
        } else if (i < N4_H + N4_WQ + N4_WO) {
            int j = i - N4_H - N4_WQ;
            ((uint2*)g_Bo)[j] = pack4(wout[j]);
        }
    }
}

// ===========================================================================
// QKV GEMM (R15-validated): C fp16 out, fp32 acc.
// BM=128, BN=128, BK=32, 512 threads (16 warps: 4M x 4N, warp tile 32x32).
// ===========================================================================
__global__ void __launch_bounds__(512, 1) tc_gemm_q(
    const __half* __restrict__ Ah, const __half* __restrict__ Bh,
    __half* __restrict__ C, int ldc, int K)
{
    extern __shared__ __align__(1024) char smem[];
    const uint32_t sbase = smem_to_u32(smem);

    const int tid  = threadIdx.x;
    const int wid  = tid >> 5;
    const int lane = tid & 31;
    const int wm   = wid & 3;
    const int wn   = wid >> 2;
    const int bm0  = blockIdx.y * 128;
    const int bn0  = blockIdx.x * 128;
    const size_t krow = (size_t)K * 2;

    const int lr  = lane & 15;
    const int lch = lane >> 4;
    const int sw  = (lr >> 1) & 3;

    float acc[2][4][4] = {};
    const int nch = K / 32;

    auto load_chunk = [&](int i, int sg) {
        const size_t kbyte = (size_t)i * 64;
        const uint32_t stb = sbase + sg * QSTAGE;
        #pragma unroll
        for (int t = 0; t < 2; ++t) {
            int lin = tid + t * 512;
            const char* src;
            uint32_t dst;
            if (lin < 512) {
                int row = lin >> 2, ch = lin & 3;
                src = (const char*)Ah + (size_t)(bm0 + row) * krow + kbyte + ch * 16;
                dst = stb + row * 64 + ((ch ^ ((row >> 1) & 3)) << 4);
            } else {
                int l2  = lin - 512;
                int row = l2 >> 2, ch = l2 & 3;
                src = (const char*)Bh + (size_t)(bn0 + row) * krow + kbyte + ch * 16;
                dst = stb + QA_TILE + row * 64 + ((ch ^ ((row >> 1) & 3)) << 4);
            }
            cp_async16(dst, src);
        }
        asm volatile("cp.async.commit_group;" ::: "memory");
    };

    load_chunk(0, 0);
    load_chunk(1, 1);
    load_chunk(2, 2);

    for (int i = 0; i < nch; ++i) {
        asm volatile("cp.async.wait_group 2;" ::: "memory");
        __syncthreads();
        if (i + 3 < nch) {
            load_chunk(i + 3, (i + 3) & 3);
        } else {
            asm volatile("cp.async.commit_group;" ::: "memory");
        }

        const uint32_t st  = sbase + (i & 3) * QSTAGE;
        const uint32_t stB = st + QA_TILE;
        const int arow = (wm * 32 + lr) * 64;
        const int brow = (wn * 32 + lr) * 64;

        #pragma unroll
        for (int ks = 0; ks < 2; ++ks) {
            const uint32_t choff = (uint32_t)(((ks * 2 + lch) ^ sw) << 4);
            uint32_t a[2][4];
            uint32_t b[4][2];

            #pragma unroll
            for (int p = 0; p < 2; ++p) {
                uint32_t r[4];
                ldm_x4(r, stB + brow + p * (16 * 64) + choff);
                b[2*p][0] = r[0]; b[2*p][1] = r[2];
                b[2*p+1][0] = r[1]; b[2*p+1][1] = r[3];
            }
            #pragma unroll
            for (int ii = 0; ii < 2; ++ii)
                ldm_x4(a[ii], st + arow + ii * (16 * 64) + choff);
            #pragma unroll
            for (int ii = 0; ii < 2; ++ii)
                #pragma unroll
                for (int jj = 0; jj < 4; ++jj)
                    mma_f16(acc[ii][jj], a[ii], b[jj]);
        }
        __syncthreads();
    }

    const int r0 = bm0 + wm * 32 + (lane >> 2);
    const int c0 = bn0 + wn * 32 + (lane & 3) * 2;
    #pragma unroll
    for (int ii = 0; ii < 2; ++ii) {
        #pragma unroll
        for (int jj = 0; jj < 4; ++jj) {
            *(uint32_t*)(C + (size_t)(r0 + ii * 16) * ldc + c0 + jj * 8)
                = pack2(acc[ii][jj][0], acc[ii][jj][1]);
            *(uint32_t*)(C + (size_t)(r0 + ii * 16 + 8) * ldc + c0 + jj * 8)
                = pack2(acc[ii][jj][2], acc[ii][jj][3]);
        }
    }
}

// ===========================================================================
// Out-proj GEMM (R15 384-thread template): C fp32.
// BM=128, BN=192, BK=32, 384 threads (12 warps: 2M x 6N, warp tile 64x32).
// ===========================================================================
__global__ void __launch_bounds__(384, 1) tc_gemm_o(
    const __half* __restrict__ Ah, const __half* __restrict__ Bh,
    float* __restrict__ C, int ldc, int K)
{
    extern __shared__ __align__(1024) char smem[];
    const uint32_t sbase = smem_to_u32(smem);
    constexpr uint32_t STAGE = GA_TILE + GB_TILE;
    constexpr int TOT = 512 + 768;

    const int tid  = threadIdx.x;
    const int wid  = tid >> 5;
    const int lane = tid & 31;
    const int wm   = wid & 1;
    const int wn   = wid >> 1;
    const int bm0  = blockIdx.y * 128;
    const int bn0  = blockIdx.x * 192;
    const size_t krow = (size_t)K * 2;

    const int lr  = lane & 15;
    const int lch = lane >> 4;
    const int sw  = (lr >> 1) & 3;

    float acc[4][4][4] = {};
    const int nch = K / 32;

    auto load_chunk = [&](int i, int sg) {
        const size_t kbyte = (size_t)i * 64;
        const uint32_t stb = sbase + sg * STAGE;
        #pragma unroll
        for (int t = 0; t < (TOT + 383) / 384; ++t) {
            int lin = tid + t * 384;
            if (lin < TOT) {
                const char* src;
                uint32_t dst;
                if (lin < 512) {
                    int row = lin >> 2, ch = lin & 3;
                    src = (const char*)Ah + (size_t)(bm0 + row) * krow + kbyte + ch * 16;
                    dst = stb + row * 64 + ((ch ^ ((row >> 1) & 3)) << 4);
                } else {
                    int l2  = lin - 512;
                    int row = l2 >> 2, ch = l2 & 3;
                    src = (const char*)Bh + (size_t)(bn0 + row) * krow + kbyte + ch * 16;
                    dst = stb + GA_TILE + row * 64 + ((ch ^ ((row >> 1) & 3)) << 4);
                }
                cp_async16(dst, src);
            }
        }
        asm volatile("cp.async.commit_group;" ::: "memory");
    };

    load_chunk(0, 0);
    load_chunk(1, 1);
    load_chunk(2, 2);

    for (int i = 0; i < nch; ++i) {
        asm volatile("cp.async.wait_group 2;" ::: "memory");
        __syncthreads();
        if (i + 3 < nch) {
            load_chunk(i + 3, (i + 3) & 3);
        } else {
            asm volatile("cp.async.commit_group;" ::: "memory");
        }

        const uint32_t st = sbase + (i & 3) * STAGE;
        const uint32_t stB = st + GA_TILE;
        const int arow = (wm * 64 + lr) * 64;
        const int brow = (wn * 32 + lr) * 64;

        #pragma unroll
        for (int ks = 0; ks < 2; ++ks) {
            const uint32_t choff = (uint32_t)(((ks * 2 + lch) ^ sw) << 4);
            uint32_t a[4][4];
            uint32_t b[4][2];

            #pragma unroll
            for (int p = 0; p < 2; ++p) {
                uint32_t r[4];
                ldm_x4(r, stB + brow + p * (16 * 64) + choff);
                b[2*p][0] = r[0]; b[2*p][1] = r[2];
                b[2*p+1][0] = r[1]; b[2*p+1][1] = r[3];
            }
            #pragma unroll
            for (int ii = 0; ii < 4; ++ii)
                ldm_x4(a[ii], st + arow + ii * (16 * 64) + choff);
            #pragma unroll
            for (int ii = 0; ii < 4; ++ii)
                #pragma unroll
                for (int jj = 0; jj < 4; ++jj)
                    mma_f16(acc[ii][jj], a[ii], b[jj]);
        }
        __syncthreads();
    }

    const int r0 = bm0 + wm * 64 + (lane >> 2);
    const int c0 = bn0 + wn * 32 + (lane & 3) * 2;
    #pragma unroll
    for (int ii = 0; ii < 4; ++ii) {
        #pragma unroll
        for (int jj = 0; jj < 4; ++jj) {
            float* p0 = C + (size_t)(r0 + ii * 16) * ldc + c0 + jj * 8;
            float* p1 = C + (size_t)(r0 + ii * 16 + 8) * ldc + c0 + jj * 8;
            *(float2*)p0 = make_float2(acc[ii][jj][0], acc[ii][jj][1]);
            *(float2*)p1 = make_float2(acc[ii][jj][2], acc[ii][jj][3]);
        }
    }
}

// ===========================================================================
// Fused RMSNorm + RoPE (reads fp16 g_qkv). One warp per (s, slot).
// ===========================================================================
__global__ void __launch_bounds__(256) norm_rope_split(
    const float* __restrict__ cosb, const float* __restrict__ sinb,
    const float* __restrict__ wq, const float* __restrict__ wk)
{
    const int unit = blockIdx.x * 8 + (threadIdx.x >> 5);
    const int lane = threadIdx.x & 31;
    const int s    = unit / 48;
    const int slot = unit % 48;
    const int grp  = slot / 24;     // 0=q, 1=k
    const int h    = slot % 24;

    const __half* p = g_qkv + (size_t)s * QKVE + grp * 3072 + h * HD;
    float4 x = unpack4(*(const uint2*)(p + lane * 4));

    float ss = x.x * x.x + x.y * x.y + x.z * x.z + x.w * x.w;
    #pragma unroll
    for (int of = 16; of > 0; of >>= 1) ss += __shfl_xor_sync(0xffffffffu, ss, of);
    float r = rsqrtf(ss * (1.0f / 128.0f) + EPSI);

    const float* w = (grp == 0) ? wq : wk;
    float4 w4 = *(const float4*)(w + lane * 4);
    float x0 = x.x * r * w4.x, x1 = x.y * r * w4.y;
    float x2 = x.z * r * w4.z, x3 = x.w * r * w4.w;

    int i = lane * 2;
    float c0 = cosb[s * 64 + i],     s0 = sinb[s * 64 + i];
    float c1 = cosb[s * 64 + i + 1], s1 = sinb[s * 64 + i + 1];
    float4 o;
    o.x = x0 * c0 - x1 * s0;
    o.y = x1 * c0 + x0 * s0;
    o.z = x2 * c1 - x3 * s1;
    o.w = x3 * c1 + x2 * s1;

    size_t off = (size_t)s * DIM_ + h * HD + lane * 4;
    if (grp == 0) {
        const float sc = 0.08838834764831845f;  // 1/sqrt(128)
        o.x *= sc; o.y *= sc; o.z *= sc; o.w *= sc;
        *(uint2*)(g_Qh + off) = pack4(o);
    } else {
        *(uint2*)(g_Kh + off) = pack4(o);
    }
}

// ===========================================================================
// Tensor-core flash attention (R13 config): no-max softmax, 256 threads,
// FQ=128, FK=128, 2-stage KV. V read from g_qkv.
// ===========================================================================
__global__ void __launch_bounds__(256, 1) flash_mma(__half* __restrict__ oh)
{
    extern __shared__ char fsm[];
    const uint32_t sQ  = smem_to_u32(fsm);
    const uint32_t kvb = sQ + FQ * FS_LD * 2;

    const int head = blockIdx.y;
    const int q0   = blockIdx.x * FQ;
    const int tid  = threadIdx.x;
    const int wid  = tid >> 5;
    const int lane = tid & 31;
    const int wr0  = wid * 16;
    const size_t hoff = (size_t)head * HD;

    const __half* ksrc = g_Kh;                     // stride DIM_
    const __half* vsrc = g_qkv + 2 * NH * HD;      // stride QKVE

    #pragma unroll
    for (int i = 0; i < 8; ++i) {
        int lin = tid + i * 256;
        int row = lin >> 4, ch = lin & 15;
        cp_async16(sQ + row * (FS_LD * 2) + ch * 16,
                   g_Qh + (size_t)(q0 + row) * DIM_ + hoff + ch * 8);
    }
    #pragma unroll
    for (int i = 0; i < 16; ++i) {
        int lin = tid + i * 256;
        int sel = lin >> 11;
        int idx = lin & 2047;
        int row = idx >> 4, ch = idx & 15;
        const __half* src = sel ? (vsrc + (size_t)row * QKVE + hoff + ch * 8)
                                : (ksrc + (size_t)row * DIM_ + hoff + ch * 8);
        cp_async16(kvb + sel * KV_TILE_BYTES + row * (FS_LD * 2) + ch * 16, src);
    }
    asm volatile("cp.async.commit_group;" ::: "memory");

    float O[16][4];
    #pragma unroll
    for (int f = 0; f < 16; ++f)
        #pragma unroll
        for (int x = 0; x < 4; ++x) O[f][x] = 0.f;
    float l_a = 0.f, l_b = 0.f;

    const int lr  = lane & 15;
    const int lch = lane >> 4;
    const int g3  = lane >> 3;
    const int r8  = lane & 7;

    const int NT = SEQ / FK;                     // 16
    for (int kt = 0; kt < NT; ++kt) {
        const int s = kt & 1;
        if (kt + 1 < NT) {
            const int k0n = (kt + 1) * FK;
            const uint32_t stb = kvb + (s ^ 1) * KV_STAGE_BYTES;
            #pragma unroll
            for (int i = 0; i < 16; ++i) {
                int lin = tid + i * 256;
                int sel = lin >> 11;
                int idx = lin & 2047;
                int row = idx >> 4, ch = idx & 15;
                const __half* src = sel
                    ? (vsrc + (size_t)(k0n + row) * QKVE + hoff + ch * 8)
                    : (ksrc + (size_t)(k0n + row) * DIM_ + hoff + ch * 8);
                cp_async16(stb + sel * KV_TILE_BYTES + row * (FS_LD * 2) + ch * 16, src);
            }
            asm volatile("cp.async.commit_group;" ::: "memory");
            asm volatile("cp.async.wait_group 1;" ::: "memory");
        } else {
            asm volatile("cp.async.wait_group 0;" ::: "memory");
        }
        __syncthreads();

        const uint32_t bK = kvb + s * KV_STAGE_BYTES;
        const uint32_t bV = bK + KV_TILE_BYTES;

        float sfr[16][4];
        #pragma unroll
        for (int f = 0; f < 16; ++f)
            #pragma unroll
            for (int x = 0; x < 4; ++x) sfr[f][x] = 0.f;

        const uint32_t aQ = sQ + (wr0 + lr) * (FS_LD * 2) + lch * 16;
        #pragma unroll
        for (int ks = 0; ks < 8; ++ks) {
            uint32_t ah[4];
            ldm_x4(ah, aQ + ks * 32);
            #pragma unroll
            for (int nfp = 0; nfp < 8; ++nfp) {
                uint32_t rh[4];
                uint32_t kaddr = (nfp * 16 + lr) * (FS_LD * 2) + lch * 16 + ks * 32;
                ldm_x4(rh, bK + kaddr);
                uint32_t b0[2] = {rh[0], rh[2]}, b1[2] = {rh[1], rh[3]};
                mma_f16(sfr[2*nfp],   ah, b0);
                mma_f16(sfr[2*nfp+1], ah, b1);
            }
        }

        #pragma unroll
        for (int ka = 0; ka < 8; ++ka) {
            float* s0 = sfr[2*ka];
            float* s1 = sfr[2*ka+1];
            s0[0] = __expf(s0[0]); l_a += s0[0];
            s0[1] = __expf(s0[1]); l_a += s0[1];
            s0[2] = __expf(s0[2]); l_b += s0[2];
            s0[3] = __expf(s0[3]); l_b += s0[3];
            s1[0] = __expf(s1[0]); l_a += s1[0];
            s1[1] = __expf(s1[1]); l_a += s1[1];
            s1[2] = __expf(s1[2]); l_b += s1[2];
            s1[3] = __expf(s1[3]); l_b += s1[3];

            uint32_t pH[4];
            pH[0] = pack2(s0[0], s0[1]);
            pH[1] = pack2(s0[2], s0[3]);
            pH[2] = pack2(s1[0], s1[1]);
            pH[3] = pack2(s1[2], s1[3]);

            #pragma unroll
            for (int nop = 0; nop < 8; ++nop) {
                uint32_t vaddr = (ka * 16 + (g3 & 1) * 8 + r8) * (FS_LD * 2)
                               + (nop * 16 + (g3 >> 1) * 8) * 2;
                uint32_t vh[4];
                ldm_x4_t(vh, bV + vaddr);
                uint32_t b0[2] = {vh[0], vh[1]}, b1[2] = {vh[2], vh[3]};
                mma_f16(O[2*nop],   pH, b0);
                mma_f16(O[2*nop+1], pH, b1);
            }
        }
        __syncthreads();
    }

    l_a += __shfl_xor_sync(0xffffffffu, l_a, 1);
    l_a += __shfl_xor_sync(0xffffffffu, l_a, 2);
    l_b += __shfl_xor_sync(0xffffffffu, l_b, 1);
    l_b += __shfl_xor_sync(0xffffffffu, l_b, 2);

    const float inva = 1.0f / l_a, invb = 1.0f / l_b;
    const int ra = q0 + wr0 + (lane >> 2);
    const int rb = ra + 8;
    const int cbase = head * HD + (lane & 3) * 2;
    #pragma unroll
    for (int f = 0; f < 16; ++f) {
        int col = cbase + f * 8;
        *(uint32_t*)(oh + (size_t)ra * DIM_ + col) = pack2(O[f][0] * inva, O[f][1] * inva);
        *(uint32_t*)(oh + (size_t)rb * DIM_ + col) = pack2(O[f][2] * invb, O[f][3] * invb);
    }
}

// ---------------------------------------------------------------------------
// Launch sequence
// ---------------------------------------------------------------------------
extern "C" void kernel_launch(void* const* d_in, const int* in_sizes, int n_in,
                              void* d_out, int out_size)
{
    const float* hidden = (const float*)d_in[0];
    const float* cosb   = (const float*)d_in[2];
    const float* sinb   = (const float*)d_in[3];
    const float* w_qkv  = (const float*)d_in[4];
    const float* nq_w   = (const float*)d_in[5];
    const float* nk_w   = (const float*)d_in[6];
    const float* w_out  = (const float*)d_in[7];
    float* out = (float*)d_out;

    __half *qkv, *Ah, *Bh, *Bo;
    cudaGetSymbolAddress((void**)&qkv, g_qkv);
    cudaGetSymbolAddress((void**)&Ah,  g_Ah);
    cudaGetSymbolAddress((void**)&Bh,  g_Bh);
    cudaGetSymbolAddress((void**)&Bo,  g_Bo);

    const int q_smem = 4 * QSTAGE;                         // 65536
    cudaFuncSetAttribute(tc_gemm_q, cudaFuncAttributeMaxDynamicSharedMemorySize, q_smem);
    const int o_smem = GNSTG * (GA_TILE + GB_TILE);        // 81920
    cudaFuncSetAttribute(tc_gemm_o, cudaFuncAttributeMaxDynamicSharedMemorySize, o_smem);
    const int fl_smem = FQ * FS_LD * 2 + 2 * KV_STAGE_BYTES;   // 174080
    cudaFuncSetAttribute(flash_mma, cudaFuncAttributeMaxDynamicSharedMemorySize, fl_smem);

    // 1) Convert hidden, w_qkv, w_out to fp16 in one launch (4 float4/thread)
    {
        int n4 = N4_H + N4_WQ + N4_WO;
        conv_all<<<(n4 + 1023) / 1024, 256>>>(
            (const float4*)hidden, (const float4*)w_qkv, (const float4*)w_out);
    }

    // 2) QKV projection -> g_qkv (fp16)
    tc_gemm_q<<<dim3(QKVE / 128, SEQ / 128), 512, q_smem>>>(
        Ah, Bh, qkv, QKVE, DIM_);

    // 3) RMSNorm + RoPE -> g_Qh, g_Kh (V stays in g_qkv)
    norm_rope_split<<<(SEQ * 48) / 8, 256>>>(cosb, sinb, nq_w, nk_w);

    // 4) Flash attention -> fp16 into Ah
    flash_mma<<<dim3(SEQ / FQ, NH), 256, fl_smem>>>(Ah);

    // 5) Output projection -> d_out (fp32)
    tc_gemm_o<<<dim3(DIM_ / 192, SEQ / 128), 384, o_smem>>>(
        Ah, Bo, out, DIM_, DIM_);
}